// round 6
// baseline (speedup 1.0000x reference)
#include <cuda_runtime.h>
#include <math.h>

#define MM 2000
#define NB 4096
#define CAND 4096
#define EDGE_MAX 4096
#define T_STATIC 0.99925f
#define TB 32
#define NT ((MM + TB - 1) / TB)        // 63 tiles per dim
#define NTILES (NT * (NT + 1) / 2)     // 2016 upper-triangle tiles
#define GRID 296                       // 2 CTAs/SM x 148 SMs — fully resident

// ---------------- device scratch (zero-initialized at module load) ----------------
__device__ int                g_candCount;
__device__ int                g_cnt;
__device__ int                g_nValid;
__device__ int                g_edgeCount;
__device__ unsigned long long g_cand[CAND];
__device__ float4             g_boxes[MM];
__device__ int                g_keep0[MM];
__device__ unsigned int       g_edges[EDGE_MAX];
__device__ volatile unsigned  g_gen;
__device__ unsigned           g_arrive;

// ---------------- grid-wide barrier (all blocks resident by construction) --------
__device__ __forceinline__ void grid_barrier() {
    __syncthreads();
    if (threadIdx.x == 0) {
        __threadfence();
        unsigned gen = g_gen;
        if (atomicAdd(&g_arrive, 1u) == (unsigned)gridDim.x - 1u) {
            atomicExch(&g_arrive, 0u);
            __threadfence();
            g_gen = gen + 1u;
        } else {
            while (g_gen == gen) __nanosleep(64);
        }
        __threadfence();
    }
    __syncthreads();
}

// ---------------- the whole pipeline in one persistent kernel --------------------
__global__ void __launch_bounds__(1024, 2) k_all(
    const float4* __restrict__ s4, int n4,
    const float2* __restrict__ score, int n,
    const float4* __restrict__ anchors,
    const float4* __restrict__ deltas,
    float* __restrict__ out)
{
    __shared__ union {
        unsigned long long keys[CAND];                       // 32 KB (rank)
        unsigned hist[NB];                                   // 16 KB (fallback)
        struct { unsigned se[EDGE_MAX]; unsigned char dead[MM]; } fin; // ~18.4 KB
    } sh;
    __shared__ int s_fb;
    int t = threadIdx.x;

    // ========== Phase 1: streaming speculative compact (32 MB read) ==========
    {
        int nthr = gridDim.x * blockDim.x;
        int tid  = blockIdx.x * blockDim.x + t;
        for (int i = tid; i < n4; i += 4 * nthr) {
            int i1 = i + nthr, i2 = i + 2 * nthr, i3 = i + 3 * nthr;
            bool b1 = i1 < n4, b2 = i2 < n4, b3 = i3 < n4;
            float4 a0 = s4[i];
            float4 a1, a2, a3;
            if (b1) a1 = s4[i1];
            if (b2) a2 = s4[i2];
            if (b3) a3 = s4[i3];
            #define EMIT(v, idx)                                                        \
                if ((v) > T_STATIC) {                                                   \
                    int pos = atomicAdd(&g_candCount, 1);                               \
                    if (pos < CAND)                                                     \
                        g_cand[pos] = ((unsigned long long)__float_as_uint(v) << 32) |  \
                                      (unsigned long long)(0xFFFFFFFFu - (idx));        \
                }
            EMIT(a0.y, 2u * (unsigned)i)
            EMIT(a0.w, 2u * (unsigned)i + 1u)
            if (b1) { EMIT(a1.y, 2u * (unsigned)i1) EMIT(a1.w, 2u * (unsigned)i1 + 1u) }
            if (b2) { EMIT(a2.y, 2u * (unsigned)i2) EMIT(a2.w, 2u * (unsigned)i2 + 1u) }
            if (b3) { EMIT(a3.y, 2u * (unsigned)i3) EMIT(a3.w, 2u * (unsigned)i3 + 1u) }
            #undef EMIT
        }
    }
    grid_barrier();

    // ========== Validation (+ never-taken exact fallback) on block 0 ==========
    if (blockIdx.x == 0) {
        if (t == 0) {
            int c = g_candCount;
            s_fb = (c < MM || c > CAND);
            if (!s_fb) { g_cnt = c; g_nValid = MM; }
            g_edgeCount = 0;
        }
        __syncthreads();
        if (s_fb) {
            __shared__ unsigned s_cut;
            __shared__ int s_cnt2;
            for (int i = t; i < NB; i += 1024) sh.hist[i] = 0u;
            __syncthreads();
            for (int i = t; i < n; i += 1024) {
                float v = score[i].y;
                if (v > 0.5f) {
                    unsigned u = __float_as_uint(v);
                    unsigned b = (u - 0x3F000000u) >> 11;
                    if (b > NB - 1u) b = NB - 1u;
                    atomicAdd(&sh.hist[b], 1u);
                }
            }
            __syncthreads();
            if (t == 0) {
                unsigned run = 0; unsigned cut = 0;
                for (int b = NB - 1; b >= 0; b--) {
                    run += sh.hist[b];
                    if (run >= (unsigned)MM) { cut = (unsigned)b; break; }
                }
                s_cut = cut; s_cnt2 = 0;
            }
            __syncthreads();
            unsigned cut = s_cut;
            for (int i = t; i < n; i += 1024) {
                float v = score[i].y;
                if (v > 0.5f) {
                    unsigned u = __float_as_uint(v);
                    unsigned b = (u - 0x3F000000u) >> 11;
                    if (b > NB - 1u) b = NB - 1u;
                    if (b >= cut) {
                        int pos = atomicAdd(&s_cnt2, 1);
                        if (pos < CAND)
                            g_cand[pos] = ((unsigned long long)u << 32) |
                                          (unsigned long long)(0xFFFFFFFFu - (unsigned)i);
                    }
                }
            }
            __syncthreads();
            if (t == 0) {
                int c2 = s_cnt2; if (c2 > CAND) c2 = CAND;
                g_cnt = c2;
                g_nValid = (c2 < MM) ? c2 : MM;
            }
        }
    }
    grid_barrier();

    // ========== Phase 2: rank-by-count + fused decode (blocks 0..127) ==========
    {
        int cnt = g_cnt;
        if ((int)blockIdx.x * 32 < cnt) {
            for (int i = t; i < CAND; i += 1024) sh.keys[i] = (i < cnt) ? g_cand[i] : 0ULL;
            __syncthreads();
            int gw = blockIdx.x * 32 + (t >> 5);
            int lane = t & 31;
            if (gw < cnt) {
                unsigned long long my = sh.keys[gw];
                int g = 0;
                for (int base = 0; base < CAND; base += 128) {
                    unsigned long long k0 = sh.keys[base       + lane];
                    unsigned long long k1 = sh.keys[base +  32 + lane];
                    unsigned long long k2 = sh.keys[base +  64 + lane];
                    unsigned long long k3 = sh.keys[base +  96 + lane];
                    g += __popc(__ballot_sync(0xffffffffu, k0 > my));
                    g += __popc(__ballot_sync(0xffffffffu, k1 > my));
                    g += __popc(__ballot_sync(0xffffffffu, k2 > my));
                    g += __popc(__ballot_sync(0xffffffffu, k3 > my));
                }
                if (lane == 0 && g < MM) {
                    unsigned idx = 0xFFFFFFFFu - (unsigned)(my & 0xFFFFFFFFull);
                    float4 a = __ldg(anchors + idx);
                    float4 d = __ldg(deltas + idx);
                    float w  = a.z - a.x;
                    float h  = a.w - a.y;
                    float cx = a.x + 0.5f * w;
                    float cy = a.y + 0.5f * h;
                    float ncx = cx + d.x * w;
                    float ncy = cy + d.y * h;
                    float nw  = w * expf(d.z);
                    float nh  = h * expf(d.w);
                    float x1 = ncx - 0.5f * nw, y1 = ncy - 0.5f * nh;
                    float x2 = ncx + 0.5f * nw, y2 = ncy + 0.5f * nh;
                    x1 = fminf(fmaxf(x1, 0.f), 1024.f);
                    y1 = fminf(fmaxf(y1, 0.f), 1024.f);
                    x2 = fminf(fmaxf(x2, 0.f), 1024.f);
                    y2 = fminf(fmaxf(y2, 0.f), 1024.f);
                    bool big = ((x2 - x1) >= 1.0f) && ((y2 - y1) >= 1.0f);
                    g_boxes[g] = make_float4(x1, y1, x2, y2);
                    g_keep0[g] = big ? 1 : 0;
                }
            }
        }
    }
    grid_barrier();

    // ========== Phase 3: pairs — one IoU per thread, tiles over grid ==========
    {
        int nV = g_nValid;
        for (int tile = blockIdx.x; tile < NTILES; tile += gridDim.x) {
            int bx = 0, rem = tile;
            while (rem >= NT - bx) { rem -= NT - bx; bx++; }
            int by = bx + rem;
            int i = bx * TB + (t >> 5);
            int j = by * TB + (t & 31);
            if (i < nV && j < nV && j > i && g_keep0[i] && g_keep0[j]) {
                float4 A = g_boxes[i];   // warp-broadcast
                float4 B = g_boxes[j];   // coalesced
                float ai = (A.z - A.x) * (A.w - A.y);
                float aj = (B.z - B.x) * (B.w - B.y);
                float ltx = fmaxf(A.x, B.x), lty = fmaxf(A.y, B.y);
                float rbx = fminf(A.z, B.z), rby = fminf(A.w, B.w);
                float iw = fmaxf(rbx - ltx, 0.f), ih = fmaxf(rby - lty, 0.f);
                float inter = iw * ih;
                float iou = inter / (ai + aj - inter + 1e-9f);
                if (iou > 0.7f) {
                    int pos = atomicAdd(&g_edgeCount, 1);
                    if (pos < EDGE_MAX) g_edges[pos] = ((unsigned)i << 16) | (unsigned)j;
                }
            }
        }
    }
    grid_barrier();

    // ========== Phase 4: block 0 resolves NMS edges & writes output ==========
    if (blockIdx.x != 0) return;
    {
        int nV = g_nValid;
        for (int m = t; m < MM; m += 1024) sh.fin.dead[m] = (m < nV && g_keep0[m]) ? 0 : 1;
        int ec = g_edgeCount; if (ec > EDGE_MAX) ec = EDGE_MAX;
        for (int i = t; i < EDGE_MAX; i += 1024) sh.fin.se[i] = (i < ec) ? g_edges[i] : 0xFFFFFFFFu;
        __syncthreads();

        if (ec > 256) {
            for (int k = 2; k <= EDGE_MAX; k <<= 1) {
                for (int j = k >> 1; j > 0; j >>= 1) {
                    for (int i = t; i < EDGE_MAX; i += 1024) {
                        int ixj = i ^ j;
                        if (ixj > i) {
                            unsigned a = sh.fin.se[i], b = sh.fin.se[ixj];
                            bool up = ((i & k) == 0);
                            if (up ? (a > b) : (a < b)) { sh.fin.se[i] = b; sh.fin.se[ixj] = a; }
                        }
                    }
                    __syncthreads();
                }
            }
        } else if (t == 0) {
            for (int a = 1; a < ec; a++) {
                unsigned key = sh.fin.se[a];
                int b = a - 1;
                while (b >= 0 && sh.fin.se[b] > key) { sh.fin.se[b + 1] = sh.fin.se[b]; b--; }
                sh.fin.se[b + 1] = key;
            }
        }
        __syncthreads();

        if (t == 0) {
            for (int e = 0; e < ec; e++) {
                unsigned u = sh.fin.se[e];
                int i = (int)(u >> 16), j = (int)(u & 0xFFFFu);
                if (!sh.fin.dead[i]) sh.fin.dead[j] = 1;
            }
        }
        __syncthreads();

        for (int m = t; m < MM; m += 1024) {
            bool keep = (sh.fin.dead[m] == 0);
            float4 b = g_boxes[m];
            out[m * 4 + 0] = keep ? b.x : 0.f;
            out[m * 4 + 1] = keep ? b.y : 0.f;
            out[m * 4 + 2] = keep ? b.z : 0.f;
            out[m * 4 + 3] = keep ? b.w : 0.f;
            out[MM * 4 + m] = keep ? 1.f : 0.f;
        }
        if (t == 0) g_candCount = 0;   // reset for next replay
    }
}

// ---------------- launch ----------------
extern "C" void kernel_launch(void* const* d_in, const int* in_sizes, int n_in,
                              void* d_out, int out_size) {
    int si = 0;
    for (int i = 1; i < n_in; i++) if (in_sizes[i] < in_sizes[si]) si = i;
    int others[2], o = 0;
    for (int i = 0; i < n_in && o < 2; i++) if (i != si) others[o++] = i;

    const float4* anchors = (const float4*)d_in[others[0]];
    const float2* score   = (const float2*)d_in[si];
    const float4* deltas  = (const float4*)d_in[others[1]];
    int n  = in_sizes[si] / 2;
    int n4 = in_sizes[si] / 4;

    k_all<<<GRID, 1024>>>((const float4*)score, n4, score, n, anchors, deltas, (float*)d_out);
}

// round 7
// speedup vs baseline: 1.1071x; 1.1071x over previous
#include <cuda_runtime.h>
#include <math.h>

#define MM 2000
#define NB 4096
#define CAND 4096
#define EDGE_MAX 4096
#define T_STATIC 0.99925f
#define TB 32
#define NT ((MM + TB - 1) / TB)        // 63 tiles per dim
#define NTILES (NT * (NT + 1) / 2)     // 2016 upper-triangle tiles

// ---------------- device scratch (zero-initialized at module load) ----------------
__device__ int                g_candCount;
__device__ int                g_cnt;
__device__ int                g_nValid;
__device__ int                g_edgeCount;
__device__ unsigned           g_done1, g_done2;
__device__ unsigned long long g_cand[CAND];
__device__ float4             g_boxes[MM];
__device__ int                g_keep0[MM];
__device__ unsigned int       g_edges[EDGE_MAX];

// ---------------- k_main: streaming speculative compact + last-block validation --
__global__ __launch_bounds__(1024) void k_main(const float4* __restrict__ s4, int n4,
                                               const float2* __restrict__ score, int n) {
    int nthr = gridDim.x * blockDim.x;
    int tid  = blockIdx.x * blockDim.x + threadIdx.x;
    for (int i = tid; i < n4; i += 4 * nthr) {
        int i1 = i + nthr, i2 = i + 2 * nthr, i3 = i + 3 * nthr;
        bool b1 = i1 < n4, b2 = i2 < n4, b3 = i3 < n4;
        float4 a0 = s4[i];
        float4 a1, a2, a3;
        if (b1) a1 = s4[i1];
        if (b2) a2 = s4[i2];
        if (b3) a3 = s4[i3];
        #define EMIT(v, idx)                                                        \
            if ((v) > T_STATIC) {                                                   \
                int pos = atomicAdd(&g_candCount, 1);                               \
                if (pos < CAND)                                                     \
                    g_cand[pos] = ((unsigned long long)__float_as_uint(v) << 32) |  \
                                  (unsigned long long)(0xFFFFFFFFu - (idx));        \
            }
        EMIT(a0.y, 2u * (unsigned)i)
        EMIT(a0.w, 2u * (unsigned)i + 1u)
        if (b1) { EMIT(a1.y, 2u * (unsigned)i1) EMIT(a1.w, 2u * (unsigned)i1 + 1u) }
        if (b2) { EMIT(a2.y, 2u * (unsigned)i2) EMIT(a2.w, 2u * (unsigned)i2 + 1u) }
        if (b3) { EMIT(a3.y, 2u * (unsigned)i3) EMIT(a3.w, 2u * (unsigned)i3 + 1u) }
        #undef EMIT
    }

    // ---- last-finishing block validates (exact fallback only if speculation failed)
    __shared__ int s_last;
    __syncthreads();
    if (threadIdx.x == 0) {
        __threadfence();
        unsigned d = atomicAdd(&g_done1, 1u);
        s_last = (d == gridDim.x - 1) ? 1 : 0;
    }
    __syncthreads();
    if (!s_last) return;

    int t = threadIdx.x;
    __shared__ int s_fb;
    if (t == 0) {
        g_done1 = 0;
        int c = g_candCount;
        s_fb = (c < MM || c > CAND);
        if (!s_fb) { g_cnt = c; g_nValid = MM; g_edgeCount = 0; }
    }
    __syncthreads();
    if (!s_fb) return;

    // pathological fallback: exact histogram selection by this one block
    __shared__ unsigned sh[NB];
    __shared__ unsigned s_cut;
    __shared__ int s_cnt2;
    for (int i = t; i < NB; i += 1024) sh[i] = 0u;
    __syncthreads();
    for (int i = t; i < n; i += 1024) {
        float v = score[i].y;
        if (v > 0.5f) {
            unsigned u = __float_as_uint(v);
            unsigned b = (u - 0x3F000000u) >> 11;
            if (b > NB - 1u) b = NB - 1u;
            atomicAdd(&sh[b], 1u);
        }
    }
    __syncthreads();
    if (t == 0) {
        unsigned run = 0; unsigned cut = 0;
        for (int b = NB - 1; b >= 0; b--) {
            run += sh[b];
            if (run >= (unsigned)MM) { cut = (unsigned)b; break; }
        }
        s_cut = cut;
        s_cnt2 = 0;
    }
    __syncthreads();
    unsigned cut = s_cut;
    for (int i = t; i < n; i += 1024) {
        float v = score[i].y;
        if (v > 0.5f) {
            unsigned u = __float_as_uint(v);
            unsigned b = (u - 0x3F000000u) >> 11;
            if (b > NB - 1u) b = NB - 1u;
            if (b >= cut) {
                int pos = atomicAdd(&s_cnt2, 1);
                if (pos < CAND)
                    g_cand[pos] = ((unsigned long long)u << 32) |
                                  (unsigned long long)(0xFFFFFFFFu - (unsigned)i);
            }
        }
    }
    __syncthreads();
    if (t == 0) {
        int c2 = s_cnt2; if (c2 > CAND) c2 = CAND;
        g_cnt = c2;
        g_nValid = (c2 < MM) ? c2 : MM;
        g_edgeCount = 0;
    }
}

// ---------------- k_rank: warp-per-candidate rank-by-count + fused decode --------
__global__ __launch_bounds__(1024) void k_rank(const float4* __restrict__ anchors,
                                               const float4* __restrict__ deltas) {
    __shared__ unsigned long long keys[CAND]; // 32 KB
    int cnt = g_cnt;
    int t = threadIdx.x;
    if ((int)blockIdx.x * 32 >= cnt) return;
    for (int i = t; i < CAND; i += 1024) keys[i] = (i < cnt) ? g_cand[i] : 0ULL;
    __syncthreads();
    int gw = blockIdx.x * 32 + (t >> 5);
    int lane = t & 31;
    if (gw >= cnt) return;
    unsigned long long my = keys[gw];
    int g = 0;
    for (int base = 0; base < CAND; base += 128) {
        unsigned long long k0 = keys[base       + lane];
        unsigned long long k1 = keys[base +  32 + lane];
        unsigned long long k2 = keys[base +  64 + lane];
        unsigned long long k3 = keys[base +  96 + lane];
        g += __popc(__ballot_sync(0xffffffffu, k0 > my));
        g += __popc(__ballot_sync(0xffffffffu, k1 > my));
        g += __popc(__ballot_sync(0xffffffffu, k2 > my));
        g += __popc(__ballot_sync(0xffffffffu, k3 > my));
    }
    if (lane == 0 && g < MM) {
        unsigned idx = 0xFFFFFFFFu - (unsigned)(my & 0xFFFFFFFFull);
        float4 a = __ldg(anchors + idx);
        float4 d = __ldg(deltas + idx);
        float w  = a.z - a.x;
        float h  = a.w - a.y;
        float cx = a.x + 0.5f * w;
        float cy = a.y + 0.5f * h;
        float ncx = cx + d.x * w;
        float ncy = cy + d.y * h;
        float nw  = w * expf(d.z);
        float nh  = h * expf(d.w);
        float x1 = ncx - 0.5f * nw, y1 = ncy - 0.5f * nh;
        float x2 = ncx + 0.5f * nw, y2 = ncy + 0.5f * nh;
        x1 = fminf(fmaxf(x1, 0.f), 1024.f);
        y1 = fminf(fmaxf(y1, 0.f), 1024.f);
        x2 = fminf(fmaxf(x2, 0.f), 1024.f);
        y2 = fminf(fmaxf(y2, 0.f), 1024.f);
        bool big = ((x2 - x1) >= 1.0f) && ((y2 - y1) >= 1.0f);
        g_boxes[g] = make_float4(x1, y1, x2, y2);
        g_keep0[g] = big ? 1 : 0;
    }
}

// ---------------- k_pairs: one block per 32x32 upper-triangle tile, one pair per
//                  thread; last-finishing block runs the NMS finalize epilogue ----
__global__ __launch_bounds__(1024) void k_pairs(float* __restrict__ out) {
    int t = threadIdx.x; // 1024
    int nV = g_nValid;

    {
        // decode linear tile id -> (bx, by), by >= bx
        int tile = blockIdx.x;
        int bx = 0, rem = tile;
        while (rem >= NT - bx) { rem -= NT - bx; bx++; }
        int by = bx + rem;
        int i = bx * TB + (t >> 5);
        int j = by * TB + (t & 31);
        if (i < nV && j < nV && j > i && g_keep0[i] && g_keep0[j]) {
            float4 A = g_boxes[i];   // warp-uniform -> L1 broadcast
            float4 B = g_boxes[j];   // coalesced across lanes
            float ai = (A.z - A.x) * (A.w - A.y);
            float aj = (B.z - B.x) * (B.w - B.y);
            float ltx = fmaxf(A.x, B.x), lty = fmaxf(A.y, B.y);
            float rbx = fminf(A.z, B.z), rby = fminf(A.w, B.w);
            float iw = fmaxf(rbx - ltx, 0.f), ih = fmaxf(rby - lty, 0.f);
            float inter = iw * ih;
            float iou = inter / (ai + aj - inter + 1e-9f);
            if (iou > 0.7f) {
                int pos = atomicAdd(&g_edgeCount, 1);
                if (pos < EDGE_MAX) g_edges[pos] = ((unsigned)i << 16) | (unsigned)j;
            }
        }
    }

    // ---- last-finishing block runs finalize ----
    __shared__ int s_last;
    __syncthreads();
    if (t == 0) {
        __threadfence();
        unsigned d = atomicAdd(&g_done2, 1u);
        s_last = (d == gridDim.x - 1) ? 1 : 0;
    }
    __syncthreads();
    if (!s_last) return;

    __shared__ unsigned char dead[MM];
    __shared__ unsigned se[EDGE_MAX]; // 16 KB
    for (int m = t; m < MM; m += 1024) dead[m] = (m < nV && g_keep0[m]) ? 0 : 1;
    int ec = g_edgeCount; if (ec > EDGE_MAX) ec = EDGE_MAX;
    for (int i = t; i < EDGE_MAX; i += 1024) se[i] = (i < ec) ? g_edges[i] : 0xFFFFFFFFu;
    __syncthreads();

    if (ec > 256) {
        for (int k = 2; k <= EDGE_MAX; k <<= 1) {
            for (int j = k >> 1; j > 0; j >>= 1) {
                for (int i = t; i < EDGE_MAX; i += 1024) {
                    int ixj = i ^ j;
                    if (ixj > i) {
                        unsigned a = se[i], b = se[ixj];
                        bool up = ((i & k) == 0);
                        if (up ? (a > b) : (a < b)) { se[i] = b; se[ixj] = a; }
                    }
                }
                __syncthreads();
            }
        }
    } else if (t == 0) {
        for (int a = 1; a < ec; a++) {
            unsigned key = se[a];
            int b = a - 1;
            while (b >= 0 && se[b] > key) { se[b + 1] = se[b]; b--; }
            se[b + 1] = key;
        }
    }
    __syncthreads();

    if (t == 0) {
        for (int e = 0; e < ec; e++) {
            unsigned u = se[e];
            int i = (int)(u >> 16), j = (int)(u & 0xFFFFu);
            if (!dead[i]) dead[j] = 1;
        }
    }
    __syncthreads();

    for (int m = t; m < MM; m += 1024) {
        bool keep = (dead[m] == 0);
        float4 b = g_boxes[m];
        out[m * 4 + 0] = keep ? b.x : 0.f;
        out[m * 4 + 1] = keep ? b.y : 0.f;
        out[m * 4 + 2] = keep ? b.z : 0.f;
        out[m * 4 + 3] = keep ? b.w : 0.f;
        out[MM * 4 + m] = keep ? 1.f : 0.f;
    }
    __syncthreads();
    if (t == 0) {   // reset state for next replay
        g_candCount = 0;
        g_edgeCount = 0;
        g_done2 = 0;
    }
}

// ---------------- launch ----------------
extern "C" void kernel_launch(void* const* d_in, const int* in_sizes, int n_in,
                              void* d_out, int out_size) {
    int si = 0;
    for (int i = 1; i < n_in; i++) if (in_sizes[i] < in_sizes[si]) si = i;
    int others[2], o = 0;
    for (int i = 0; i < n_in && o < 2; i++) if (i != si) others[o++] = i;

    const float4* anchors = (const float4*)d_in[others[0]];
    const float2* score   = (const float2*)d_in[si];
    const float4* deltas  = (const float4*)d_in[others[1]];
    int n  = in_sizes[si] / 2;
    int n4 = in_sizes[si] / 4;

    k_main<<<296, 1024>>>((const float4*)score, n4, score, n);
    k_rank<<<CAND / 32, 1024>>>(anchors, deltas);
    k_pairs<<<NTILES, 1024>>>((float*)d_out);
}